// round 12
// baseline (speedup 1.0000x reference)
#include <cuda_runtime.h>

#define BATCH 4
#define C 256
#define H 256
#define W 256
#define S 8
#define HP 32
#define WP 32
#define N 1024     // HP*WP tokens
#define KC 32      // key channels

typedef unsigned int uint;

// ---------------- device scratch (no allocs allowed) ----------------
__device__ float g_xf[BATCH * C * N];        // pooled features  [b][c][n]
__device__ float g_qT[BATCH * N * KC];       // q transposed     [b][n][k]
__device__ float g_kT[BATCH * N * KC];       // k transposed     [b][m][k]
__device__ float g_v[BATCH * C * N];         // v (tf32-rounded) [b][c][n]
__device__ float g_attn[BATCH * N * N];      // exp(energy), unnormalized [b][n][m]
__device__ float g_rsum[BATCH * N];          // softmax row sums
__device__ float g_out[BATCH * C * N];       // attn output      [b][c][n]

__device__ __forceinline__ float to_tf32(float x) {
    float r; asm("cvt.rna.tf32.f32 %0, %1;" : "=f"(r) : "f"(x)); return r;
}

__device__ __forceinline__ void mma_tf32(float* d, const uint* a, const uint* b) {
    asm volatile(
        "mma.sync.aligned.m16n8k8.row.col.f32.tf32.tf32.f32 "
        "{%0,%1,%2,%3}, {%4,%5,%6,%7}, {%8,%9}, {%0,%1,%2,%3};"
        : "+f"(d[0]), "+f"(d[1]), "+f"(d[2]), "+f"(d[3])
        : "r"(a[0]), "r"(a[1]), "r"(a[2]), "r"(a[3]), "r"(b[0]), "r"(b[1]));
}

__device__ __forceinline__ void cp16(uint smem_addr, const void* gptr) {
    asm volatile("cp.async.ca.shared.global [%0], [%1], 16;"
                 :: "r"(smem_addr), "l"(gptr));
}

// FMA-pipe exp: exp(x) = 2^(x*log2e), magic-number round + deg-5 poly + exp-bit ldexp.
__device__ __forceinline__ float fast_expf(float x) {
    x = fmaxf(x, -80.0f);
    float y = x * 1.4426950408889634f;
    float z = y + 12582912.0f;
    int   e = __float_as_int(z);
    float n = z - 12582912.0f;
    float f = y - n;
    float p = 0.0013333558146428443f;
    p = fmaf(p, f, 0.009618129107628477f);
    p = fmaf(p, f, 0.05550410866482158f);
    p = fmaf(p, f, 0.2402265069591007f);
    p = fmaf(p, f, 0.6931471805599453f);
    p = fmaf(p, f, 1.0f);
    return __int_as_float(__float_as_int(p) + (e << 23));
}

// ---------------- kernel 1: 8x8 avg pool ----------------
__global__ void avgpool_kernel(const float* __restrict__ f) {
    int idx = blockIdx.x * blockDim.x + threadIdx.x;   // over BATCH*C*N
    int n  = idx & (N - 1);
    int bc = idx >> 10;
    int wp = n & (WP - 1);
    int hp = n >> 5;
    const float* src = f + ((size_t)bc * H + (size_t)hp * S) * W + (size_t)wp * S;
    float s = 0.f;
#pragma unroll
    for (int r = 0; r < S; r++) {
        float4 a = *(const float4*)(src + (size_t)r * W);
        float4 b = *(const float4*)(src + (size_t)r * W + 4);
        s += a.x + a.y + a.z + a.w + b.x + b.y + b.z + b.w;
    }
    g_xf[idx] = s * (1.f / 64.f);
}

// ---------------- kernel 2: q/k/v via tf32 HMMA ----------------
// rgroup 0: rows 0..31 = qw, 32..63 = kw (outputs stored TRANSPOSED [n][k]).
// rgroup 1..4: vw rows (g-1)*64.. (output [c][n], tf32-rounded).
#define QLDA 36
#define QLDB 72
__global__ void qkv_mma_kernel(const float* __restrict__ qw, const float* __restrict__ qb,
                               const float* __restrict__ kw, const float* __restrict__ kb,
                               const float* __restrict__ vw, const float* __restrict__ vb) {
    int b  = blockIdx.z;
    int g  = blockIdx.y;
    int n0 = blockIdx.x * 64;

    __shared__ __align__(16) float As[2][64 * QLDA];   // A[m=64][k=32]
    __shared__ __align__(16) float Bs[2][32 * QLDB];   // B[k=32][n=64]
    __shared__ float bsh[64];

    int tid  = threadIdx.x;
    int lane = tid & 31, wid = tid >> 5;
    int wm = (wid & 1) * 32;
    int wn = (wid >> 1) * 16;
    int r4 = lane >> 2, q4 = lane & 3;

    int rowA0 = tid >> 3;          // 0..31
    int segA  = tid & 7;
    int rowB0 = tid >> 4;          // 0..15
    int segB  = tid & 15;

    const float* arow0;
    const float* arow1;
    int row1 = rowA0 + 32;
    if (g == 0) {
        arow0 = qw + (size_t)rowA0 * C;
        arow1 = kw + (size_t)(row1 - 32) * C;
    } else {
        arow0 = vw + (size_t)((g - 1) * 64 + rowA0) * C;
        arow1 = vw + (size_t)((g - 1) * 64 + row1) * C;
    }
    if (tid < 64) {
        float bv;
        if (g == 0) bv = (tid < 32) ? qb[tid] : kb[tid - 32];
        else        bv = vb[(g - 1) * 64 + tid];
        bsh[tid] = bv;
    }

    const float* xfb = g_xf + (size_t)b * C * N;

    float acc[2][2][4];
#pragma unroll
    for (int am = 0; am < 2; am++)
#pragma unroll
        for (int an = 0; an < 2; an++)
#pragma unroll
            for (int j = 0; j < 4; j++) acc[am][an][j] = 0.f;

    {
        cp16((uint)__cvta_generic_to_shared(&As[0][rowA0 * QLDA + segA * 4]), arow0 + segA * 4);
        cp16((uint)__cvta_generic_to_shared(&As[0][row1  * QLDA + segA * 4]), arow1 + segA * 4);
        cp16((uint)__cvta_generic_to_shared(&Bs[0][rowB0 * QLDB + segB * 4]),
             xfb + (size_t)rowB0 * N + n0 + segB * 4);
        cp16((uint)__cvta_generic_to_shared(&Bs[0][(rowB0 + 16) * QLDB + segB * 4]),
             xfb + (size_t)(rowB0 + 16) * N + n0 + segB * 4);
        asm volatile("cp.async.commit_group;");
    }

    for (int ch = 0; ch < 8; ch++) {          // C/32 = 8 chunks
        int s = ch & 1;
        if (ch + 1 < 8) {
            int c1 = (ch + 1) * 32;
            cp16((uint)__cvta_generic_to_shared(&As[s ^ 1][rowA0 * QLDA + segA * 4]), arow0 + c1 + segA * 4);
            cp16((uint)__cvta_generic_to_shared(&As[s ^ 1][row1  * QLDA + segA * 4]), arow1 + c1 + segA * 4);
            cp16((uint)__cvta_generic_to_shared(&Bs[s ^ 1][rowB0 * QLDB + segB * 4]),
                 xfb + (size_t)(c1 + rowB0) * N + n0 + segB * 4);
            cp16((uint)__cvta_generic_to_shared(&Bs[s ^ 1][(rowB0 + 16) * QLDB + segB * 4]),
                 xfb + (size_t)(c1 + rowB0 + 16) * N + n0 + segB * 4);
            asm volatile("cp.async.commit_group;");
            asm volatile("cp.async.wait_group 1;");
        } else {
            asm volatile("cp.async.wait_group 0;");
        }
        __syncthreads();

        const uint* Ass = (const uint*)As[s];
        const uint* Bss = (const uint*)Bs[s];
#pragma unroll
        for (int k8 = 0; k8 < 32; k8 += 8) {
            uint a[2][4], bb[2][2];
#pragma unroll
            for (int am = 0; am < 2; am++) {
                int base = (wm + am * 16 + r4) * QLDA + k8 + q4;
                a[am][0] = Ass[base];
                a[am][1] = Ass[base + 8 * QLDA];
                a[am][2] = Ass[base + 4];
                a[am][3] = Ass[base + 8 * QLDA + 4];
            }
#pragma unroll
            for (int an = 0; an < 2; an++) {
                int nb = wn + an * 8 + r4;
                bb[an][0] = Bss[(k8 + q4) * QLDB + nb];
                bb[an][1] = Bss[(k8 + q4 + 4) * QLDB + nb];
            }
#pragma unroll
            for (int am = 0; am < 2; am++)
#pragma unroll
                for (int an = 0; an < 2; an++)
                    mma_tf32(acc[am][an], a[am], bb[an]);
        }
        __syncthreads();
    }

    int cc = (lane & 3) * 2;
    if (g == 0) {
        // transposed scattered stores: qT/kT [n][kc]
        float* QT = g_qT + (size_t)b * N * KC;
        float* KT = g_kT + (size_t)b * N * KC;
#pragma unroll
        for (int am = 0; am < 2; am++)
#pragma unroll
            for (int an = 0; an < 2; an++) {
                int r  = wm + am * 16 + r4;
                int nc = n0 + wn + an * 8 + cc;
#pragma unroll
                for (int dr = 0; dr < 2; dr++) {      // rows r, r+8
                    int rr = r + dr * 8;
                    float d0 = acc[am][an][dr * 2 + 0] + bsh[rr];
                    float d1 = acc[am][an][dr * 2 + 1] + bsh[rr];
                    float* dst = (rr < 32) ? (QT + rr) : (KT + rr - 32);
                    dst[(size_t)nc * KC]       = to_tf32(d0);
                    dst[(size_t)(nc + 1) * KC] = to_tf32(d1);
                }
            }
    } else {
        float* V = g_v + (size_t)b * C * N + (size_t)(g - 1) * 64 * N;
#pragma unroll
        for (int am = 0; am < 2; am++)
#pragma unroll
            for (int an = 0; an < 2; an++) {
                int r  = wm + am * 16 + r4;
                int nc = n0 + wn + an * 8 + cc;
                float2 lo; lo.x = to_tf32(acc[am][an][0] + bsh[r]);     lo.y = to_tf32(acc[am][an][1] + bsh[r]);
                float2 hi; hi.x = to_tf32(acc[am][an][2] + bsh[r + 8]); hi.y = to_tf32(acc[am][an][3] + bsh[r + 8]);
                *(float2*)(V + (size_t)r * N + nc)       = lo;
                *(float2*)(V + (size_t)(r + 8) * N + nc) = hi;
            }
    }
}

// ---------------- kernel 3: energy via HMMA + exp (unnormalized) + row sums ----------------
#define ALD 36
__global__ void attn_mma_kernel() {
    int b  = blockIdx.y;
    int n0 = blockIdx.x * 16;
    int tid  = threadIdx.x;
    int lane = tid & 31, w = tid >> 5;
    int r4 = lane >> 2, q4 = lane & 3;

    __shared__ __align__(16) float Asm[16 * ALD];        // qT tile [16 n][32 k]
    __shared__ __align__(16) float Bs[2][128 * ALD];     // kT chunk [128 m][32 k]
    __shared__ float red[16][8];

    const float* QT = g_qT + (size_t)b * N * KC;
    const float* KT = g_kT + (size_t)b * N * KC;
    float* P = g_attn + (size_t)b * N * N;

    if (tid < 128) {
        int row = tid >> 3, seg = tid & 7;
        cp16((uint)__cvta_generic_to_shared(&Asm[row * ALD + seg * 4]),
             QT + (size_t)(n0 + row) * KC + seg * 4);
    }
    {
#pragma unroll
        for (int i = 0; i < 4; i++) {
            int slot = tid + i * 256;
            int rr = slot >> 3, ss = slot & 7;
            cp16((uint)__cvta_generic_to_shared(&Bs[0][rr * ALD + ss * 4]),
                 KT + (size_t)rr * KC + ss * 4);
        }
        asm volatile("cp.async.commit_group;");
    }

    uint a_all[4][4];
    float rs0 = 0.f, rs1 = 0.f;
    const float scale = 0.17677669529663687f;   // 32^-0.5

    for (int ch = 0; ch < 8; ch++) {
        int s = ch & 1;
        if (ch + 1 < 8) {
            int m1 = (ch + 1) * 128;
#pragma unroll
            for (int i = 0; i < 4; i++) {
                int slot = tid + i * 256;
                int rr = slot >> 3, ss = slot & 7;
                cp16((uint)__cvta_generic_to_shared(&Bs[s ^ 1][rr * ALD + ss * 4]),
                     KT + (size_t)(m1 + rr) * KC + ss * 4);
            }
            asm volatile("cp.async.commit_group;");
            asm volatile("cp.async.wait_group 1;");
        } else {
            asm volatile("cp.async.wait_group 0;");
        }
        __syncthreads();

        if (ch == 0) {
            const uint* Au = (const uint*)Asm;
#pragma unroll
            for (int k8 = 0; k8 < 4; k8++) {
                int base = r4 * ALD + k8 * 8 + q4;
                a_all[k8][0] = Au[base];
                a_all[k8][1] = Au[base + 8 * ALD];
                a_all[k8][2] = Au[base + 4];
                a_all[k8][3] = Au[base + 8 * ALD + 4];
            }
        }

        const uint* Bu = (const uint*)Bs[s];
        float acc[2][4];
#pragma unroll
        for (int at = 0; at < 2; at++)
#pragma unroll
            for (int j = 0; j < 4; j++) acc[at][j] = 0.f;

#pragma unroll
        for (int k8 = 0; k8 < 4; k8++) {
            uint bb[2][2];
#pragma unroll
            for (int at = 0; at < 2; at++) {
                int mb = (w * 16 + at * 8 + r4) * ALD + k8 * 8 + q4;
                bb[at][0] = Bu[mb];
                bb[at][1] = Bu[mb + 4];
            }
#pragma unroll
            for (int at = 0; at < 2; at++)
                mma_tf32(acc[at], a_all[k8], bb[at]);
        }

        // exp + store + row-sum accumulation
        int cc = q4 * 2;
        int mbase = ch * 128 + w * 16;
#pragma unroll
        for (int at = 0; at < 2; at++) {
            float e0 = fast_expf(acc[at][0] * scale);
            float e1 = fast_expf(acc[at][1] * scale);
            float e2 = fast_expf(acc[at][2] * scale);
            float e3 = fast_expf(acc[at][3] * scale);
            rs0 += e0 + e1;
            rs1 += e2 + e3;
            int mc = mbase + at * 8 + cc;
            float2 lo; lo.x = to_tf32(e0); lo.y = to_tf32(e1);
            float2 hi; hi.x = to_tf32(e2); hi.y = to_tf32(e3);
            *(float2*)(P + (size_t)(n0 + r4) * N + mc)     = lo;
            *(float2*)(P + (size_t)(n0 + r4 + 8) * N + mc) = hi;
        }
        __syncthreads();
    }

    rs0 += __shfl_xor_sync(0xFFFFFFFFu, rs0, 1);
    rs0 += __shfl_xor_sync(0xFFFFFFFFu, rs0, 2);
    rs1 += __shfl_xor_sync(0xFFFFFFFFu, rs1, 1);
    rs1 += __shfl_xor_sync(0xFFFFFFFFu, rs1, 2);
    if (q4 == 0) { red[r4][w] = rs0; red[r4 + 8][w] = rs1; }
    __syncthreads();
    if (tid < 16) {
        float s = 0.f;
#pragma unroll
        for (int j = 0; j < 8; j++) s += red[tid][j];
        g_rsum[(size_t)b * N + n0 + tid] = s;
    }
}

// ---------------- kernel 4: out = v @ E^T (scaled by 1/rsum) via tf32 HMMA ----------------
// R9 tiling (64x64, 8 warps of 32x16) but GBK=64: half the barriers/commit rounds.
#define GBM 64
#define GBN 64
#define GBK 64
#define LDP 68   // 68 mod 32 = 4 -> scalar fragment loads conflict-free (as LDP=36)
#define NCHUNK (N / GBK)
#define GEMM_SMEM_BYTES (2 * (GBM + GBN) * LDP * 4)
__global__ __launch_bounds__(256) void out_gemm_kernel() {
    extern __shared__ __align__(16) uint dsm[];
    uint* VsB = dsm;                       // [2][GBM*LDP]
    uint* PsB = dsm + 2 * GBM * LDP;       // [2][GBN*LDP]

    int b  = blockIdx.z;
    int c0 = blockIdx.y * GBM;
    int n0 = blockIdx.x * GBN;

    int tid  = threadIdx.x;      // 0..255
    int lane = tid & 31, wid = tid >> 5;
    int wm = (wid & 1) * 32;
    int wn = (wid >> 1) * 16;

    const uint* V = (const uint*)g_v    + (size_t)b * C * N;
    const uint* P = (const uint*)g_attn + (size_t)b * N * N;

    // copy slots: 64 rows x 16 segs = 1024 per array; 256 threads x 4 iters
    int crow = tid >> 4;          // 0..15
    int cseg = (tid & 15) * 4;

    float acc[2][2][4];
#pragma unroll
    for (int am = 0; am < 2; am++)
#pragma unroll
        for (int an = 0; an < 2; an++)
#pragma unroll
            for (int j = 0; j < 4; j++) acc[am][an][j] = 0.f;

    int r4 = lane >> 2, q4 = lane & 3;

    // stage-0 prefetch
    {
#pragma unroll
        for (int i = 0; i < 4; i++) {
            int row = crow + i * 16;
            cp16((uint)__cvta_generic_to_shared(&VsB[row * LDP + cseg]),
                 V + (size_t)(c0 + row) * N + cseg);
            cp16((uint)__cvta_generic_to_shared(&PsB[row * LDP + cseg]),
                 P + (size_t)(n0 + row) * N + cseg);
        }
        asm volatile("cp.async.commit_group;");
    }

    for (int ch = 0; ch < NCHUNK; ch++) {
        int s = ch & 1;
        if (ch + 1 < NCHUNK) {
            int m1 = (ch + 1) * GBK;
            uint* Vd = VsB + (s ^ 1) * GBM * LDP;
            uint* Pd = PsB + (s ^ 1) * GBN * LDP;
#pragma unroll
            for (int i = 0; i < 4; i++) {
                int row = crow + i * 16;
                cp16((uint)__cvta_generic_to_shared(&Vd[row * LDP + cseg]),
                     V + (size_t)(c0 + row) * N + m1 + cseg);
                cp16((uint)__cvta_generic_to_shared(&Pd[row * LDP + cseg]),
                     P + (size_t)(n0 + row) * N + m1 + cseg);
            }
            asm volatile("cp.async.commit_group;");
            asm volatile("cp.async.wait_group 1;");
        } else {
            asm volatile("cp.async.wait_group 0;");
        }
        __syncthreads();

        const uint* Vss = VsB + s * GBM * LDP;
        const uint* Pss = PsB + s * GBN * LDP;
#pragma unroll
        for (int k8 = 0; k8 < GBK; k8 += 8) {
            uint a[2][4], bb[2][2];
#pragma unroll
            for (int am = 0; am < 2; am++) {
                int base = (wm + am * 16 + r4) * LDP + k8 + q4;
                a[am][0] = Vss[base];
                a[am][1] = Vss[base + 8 * LDP];
                a[am][2] = Vss[base + 4];
                a[am][3] = Vss[base + 8 * LDP + 4];
            }
#pragma unroll
            for (int an = 0; an < 2; an++) {
                int base = (wn + an * 8 + r4) * LDP + k8 + q4;
                bb[an][0] = Pss[base];
                bb[an][1] = Pss[base + 4];
            }
#pragma unroll
            for (int am = 0; am < 2; am++)
#pragma unroll
                for (int an = 0; an < 2; an++)
                    mma_tf32(acc[am][an], a[am], bb[an]);
        }
        __syncthreads();
    }

    float* O = g_out + (size_t)b * C * N;
    const float* RS = g_rsum + (size_t)b * N;
    int cc = (lane & 3) * 2;
    float inv[2][2];
#pragma unroll
    for (int an = 0; an < 2; an++) {
        int nc = n0 + wn + an * 8 + cc;
        inv[an][0] = 1.0f / RS[nc];
        inv[an][1] = 1.0f / RS[nc + 1];
    }
#pragma unroll
    for (int am = 0; am < 2; am++)
#pragma unroll
        for (int an = 0; an < 2; an++) {
            int cr = c0 + wm + am * 16 + r4;
            int ncol = n0 + wn + an * 8 + cc;
            float2 lo; lo.x = acc[am][an][0] * inv[an][0]; lo.y = acc[am][an][1] * inv[an][1];
            float2 hi; hi.x = acc[am][an][2] * inv[an][0]; hi.y = acc[am][an][3] * inv[an][1];
            *(float2*)(O + (size_t)cr * N + ncol)       = lo;
            *(float2*)(O + (size_t)(cr + 8) * N + ncol) = hi;
        }
}

// ---------------- kernel 5: nearest 8x upsample + residual ----------------
__global__ void upsample_add_kernel(const float* __restrict__ f, float* __restrict__ out) {
    size_t idx = (size_t)blockIdx.x * blockDim.x + threadIdx.x;  // over B*C*H*W/4
    int w4 = (int)(idx & 63);
    int h  = (int)((idx >> 6) & 255);
    size_t bc = idx >> 14;
    int hp = h >> 3;
    int wp = w4 >> 1;
    float s = g_out[bc * N + (size_t)hp * WP + wp];
    float4 a = ((const float4*)f)[idx];
    a.x += s; a.y += s; a.z += s; a.w += s;
    ((float4*)out)[idx] = a;
}

// ---------------- launch ----------------
extern "C" void kernel_launch(void* const* d_in, const int* in_sizes, int n_in,
                              void* d_out, int out_size) {
    const float* f  = (const float*)d_in[0];
    const float* qw = (const float*)d_in[1];
    const float* qb = (const float*)d_in[2];
    const float* kw = (const float*)d_in[3];
    const float* kb = (const float*)d_in[4];
    const float* vw = (const float*)d_in[5];
    const float* vb = (const float*)d_in[6];
    float* out = (float*)d_out;

    cudaFuncSetAttribute(out_gemm_kernel,
                         cudaFuncAttributeMaxDynamicSharedMemorySize, GEMM_SMEM_BYTES);

    avgpool_kernel<<<(BATCH * C * N) / 256, 256>>>(f);
    qkv_mma_kernel<<<dim3(N / 64, 5, BATCH), 256>>>(qw, qb, kw, kb, vw, vb);
    attn_mma_kernel<<<dim3(N / 16, BATCH), 256>>>();
    out_gemm_kernel<<<dim3(N / GBN, C / GBM, BATCH), 256, GEMM_SMEM_BYTES>>>();
    upsample_add_kernel<<<(BATCH * C * H * (W / 4)) / 256, 256>>>(f, out);
}

// round 13
// speedup vs baseline: 1.2829x; 1.2829x over previous
#include <cuda_runtime.h>
#include <cuda_bf16.h>

#define BATCH 4
#define C 256
#define H 256
#define W 256
#define S 8
#define HP 32
#define WP 32
#define N 1024     // HP*WP tokens
#define KC 32      // key channels
#define NU (N / 2) // uints (bf16 pairs) per token row

typedef unsigned int uint;

// ---------------- device scratch (no allocs allowed) ----------------
__device__ float g_xf[BATCH * C * N];           // pooled features  [b][c][n]
__device__ float g_qT[BATCH * N * KC];          // q transposed     [b][n][k]
__device__ float g_kT[BATCH * N * KC];          // k transposed     [b][m][k]
__device__ uint  g_v[BATCH * C * NU];           // v bf16x2         [b][c][m/2]
__device__ uint  g_attn[BATCH * N * NU];        // exp(energy) bf16x2 [b][n][m/2]
__device__ float g_rsum[BATCH * N];             // softmax row sums
__device__ float g_out[BATCH * C * N];          // attn output      [b][c][n]

__device__ __forceinline__ float to_tf32(float x) {
    float r; asm("cvt.rna.tf32.f32 %0, %1;" : "=f"(r) : "f"(x)); return r;
}

__device__ __forceinline__ uint pack_bf2(float lo, float hi) {
    __nv_bfloat162 t = __floats2bfloat162_rn(lo, hi);   // x=lo(low half), y=hi
    return *(uint*)&t;
}

__device__ __forceinline__ void mma_tf32(float* d, const uint* a, const uint* b) {
    asm volatile(
        "mma.sync.aligned.m16n8k8.row.col.f32.tf32.tf32.f32 "
        "{%0,%1,%2,%3}, {%4,%5,%6,%7}, {%8,%9}, {%0,%1,%2,%3};"
        : "+f"(d[0]), "+f"(d[1]), "+f"(d[2]), "+f"(d[3])
        : "r"(a[0]), "r"(a[1]), "r"(a[2]), "r"(a[3]), "r"(b[0]), "r"(b[1]));
}

__device__ __forceinline__ void mma_bf16(float* d, const uint* a, const uint* b) {
    asm volatile(
        "mma.sync.aligned.m16n8k16.row.col.f32.bf16.bf16.f32 "
        "{%0,%1,%2,%3}, {%4,%5,%6,%7}, {%8,%9}, {%0,%1,%2,%3};"
        : "+f"(d[0]), "+f"(d[1]), "+f"(d[2]), "+f"(d[3])
        : "r"(a[0]), "r"(a[1]), "r"(a[2]), "r"(a[3]), "r"(b[0]), "r"(b[1]));
}

__device__ __forceinline__ void cp16(uint smem_addr, const void* gptr) {
    asm volatile("cp.async.ca.shared.global [%0], [%1], 16;"
                 :: "r"(smem_addr), "l"(gptr));
}

// FMA-pipe exp: exp(x) = 2^(x*log2e), magic-number round + deg-5 poly + exp-bit ldexp.
__device__ __forceinline__ float fast_expf(float x) {
    x = fmaxf(x, -80.0f);
    float y = x * 1.4426950408889634f;
    float z = y + 12582912.0f;
    int   e = __float_as_int(z);
    float n = z - 12582912.0f;
    float f = y - n;
    float p = 0.0013333558146428443f;
    p = fmaf(p, f, 0.009618129107628477f);
    p = fmaf(p, f, 0.05550410866482158f);
    p = fmaf(p, f, 0.2402265069591007f);
    p = fmaf(p, f, 0.6931471805599453f);
    p = fmaf(p, f, 1.0f);
    return __int_as_float(__float_as_int(p) + (e << 23));
}

// ---------------- kernel 1: 8x8 avg pool ----------------
__global__ void avgpool_kernel(const float* __restrict__ f) {
    int idx = blockIdx.x * blockDim.x + threadIdx.x;   // over BATCH*C*N
    int n  = idx & (N - 1);
    int bc = idx >> 10;
    int wp = n & (WP - 1);
    int hp = n >> 5;
    const float* src = f + ((size_t)bc * H + (size_t)hp * S) * W + (size_t)wp * S;
    float s = 0.f;
#pragma unroll
    for (int r = 0; r < S; r++) {
        float4 a = *(const float4*)(src + (size_t)r * W);
        float4 b = *(const float4*)(src + (size_t)r * W + 4);
        s += a.x + a.y + a.z + a.w + b.x + b.y + b.z + b.w;
    }
    g_xf[idx] = s * (1.f / 64.f);
}

// ---------------- kernel 2: q/k/v via tf32 HMMA ----------------
// rgroup 0: rows 0..31 = qw, 32..63 = kw (outputs stored TRANSPOSED [n][k], fp32).
// rgroup 1..4: vw rows (g-1)*64.. -> g_v bf16x2 [c][m/2].
#define QLDA 36
#define QLDB 72
__global__ void qkv_mma_kernel(const float* __restrict__ qw, const float* __restrict__ qb,
                               const float* __restrict__ kw, const float* __restrict__ kb,
                               const float* __restrict__ vw, const float* __restrict__ vb) {
    int b  = blockIdx.z;
    int g  = blockIdx.y;
    int n0 = blockIdx.x * 64;

    __shared__ __align__(16) float As[2][64 * QLDA];   // A[m=64][k=32]
    __shared__ __align__(16) float Bs[2][32 * QLDB];   // B[k=32][n=64]
    __shared__ float bsh[64];

    int tid  = threadIdx.x;
    int lane = tid & 31, wid = tid >> 5;
    int wm = (wid & 1) * 32;
    int wn = (wid >> 1) * 16;
    int r4 = lane >> 2, q4 = lane & 3;

    int rowA0 = tid >> 3;          // 0..31
    int segA  = tid & 7;
    int rowB0 = tid >> 4;          // 0..15
    int segB  = tid & 15;

    const float* arow0;
    const float* arow1;
    int row1 = rowA0 + 32;
    if (g == 0) {
        arow0 = qw + (size_t)rowA0 * C;
        arow1 = kw + (size_t)(row1 - 32) * C;
    } else {
        arow0 = vw + (size_t)((g - 1) * 64 + rowA0) * C;
        arow1 = vw + (size_t)((g - 1) * 64 + row1) * C;
    }
    if (tid < 64) {
        float bv;
        if (g == 0) bv = (tid < 32) ? qb[tid] : kb[tid - 32];
        else        bv = vb[(g - 1) * 64 + tid];
        bsh[tid] = bv;
    }

    const float* xfb = g_xf + (size_t)b * C * N;

    float acc[2][2][4];
#pragma unroll
    for (int am = 0; am < 2; am++)
#pragma unroll
        for (int an = 0; an < 2; an++)
#pragma unroll
            for (int j = 0; j < 4; j++) acc[am][an][j] = 0.f;

    {
        cp16((uint)__cvta_generic_to_shared(&As[0][rowA0 * QLDA + segA * 4]), arow0 + segA * 4);
        cp16((uint)__cvta_generic_to_shared(&As[0][row1  * QLDA + segA * 4]), arow1 + segA * 4);
        cp16((uint)__cvta_generic_to_shared(&Bs[0][rowB0 * QLDB + segB * 4]),
             xfb + (size_t)rowB0 * N + n0 + segB * 4);
        cp16((uint)__cvta_generic_to_shared(&Bs[0][(rowB0 + 16) * QLDB + segB * 4]),
             xfb + (size_t)(rowB0 + 16) * N + n0 + segB * 4);
        asm volatile("cp.async.commit_group;");
    }

    for (int ch = 0; ch < 8; ch++) {          // C/32 = 8 chunks
        int s = ch & 1;
        if (ch + 1 < 8) {
            int c1 = (ch + 1) * 32;
            cp16((uint)__cvta_generic_to_shared(&As[s ^ 1][rowA0 * QLDA + segA * 4]), arow0 + c1 + segA * 4);
            cp16((uint)__cvta_generic_to_shared(&As[s ^ 1][row1  * QLDA + segA * 4]), arow1 + c1 + segA * 4);
            cp16((uint)__cvta_generic_to_shared(&Bs[s ^ 1][rowB0 * QLDB + segB * 4]),
                 xfb + (size_t)(c1 + rowB0) * N + n0 + segB * 4);
            cp16((uint)__cvta_generic_to_shared(&Bs[s ^ 1][(rowB0 + 16) * QLDB + segB * 4]),
                 xfb + (size_t)(c1 + rowB0 + 16) * N + n0 + segB * 4);
            asm volatile("cp.async.commit_group;");
            asm volatile("cp.async.wait_group 1;");
        } else {
            asm volatile("cp.async.wait_group 0;");
        }
        __syncthreads();

        const uint* Ass = (const uint*)As[s];
        const uint* Bss = (const uint*)Bs[s];
#pragma unroll
        for (int k8 = 0; k8 < 32; k8 += 8) {
            uint a[2][4], bb[2][2];
#pragma unroll
            for (int am = 0; am < 2; am++) {
                int base = (wm + am * 16 + r4) * QLDA + k8 + q4;
                a[am][0] = Ass[base];
                a[am][1] = Ass[base + 8 * QLDA];
                a[am][2] = Ass[base + 4];
                a[am][3] = Ass[base + 8 * QLDA + 4];
            }
#pragma unroll
            for (int an = 0; an < 2; an++) {
                int nb = wn + an * 8 + r4;
                bb[an][0] = Bss[(k8 + q4) * QLDB + nb];
                bb[an][1] = Bss[(k8 + q4 + 4) * QLDB + nb];
            }
#pragma unroll
            for (int am = 0; am < 2; am++)
#pragma unroll
                for (int an = 0; an < 2; an++)
                    mma_tf32(acc[am][an], a[am], bb[an]);
        }
        __syncthreads();
    }

    int cc = (lane & 3) * 2;
    if (g == 0) {
        // transposed scattered stores: qT/kT [n][kc], fp32 (tf32-rounded)
        float* QT = g_qT + (size_t)b * N * KC;
        float* KT = g_kT + (size_t)b * N * KC;
#pragma unroll
        for (int am = 0; am < 2; am++)
#pragma unroll
            for (int an = 0; an < 2; an++) {
                int r  = wm + am * 16 + r4;
                int nc = n0 + wn + an * 8 + cc;
#pragma unroll
                for (int dr = 0; dr < 2; dr++) {      // rows r, r+8
                    int rr = r + dr * 8;
                    float d0 = acc[am][an][dr * 2 + 0] + bsh[rr];
                    float d1 = acc[am][an][dr * 2 + 1] + bsh[rr];
                    float* dst = (rr < 32) ? (QT + rr) : (KT + rr - 32);
                    dst[(size_t)nc * KC]       = to_tf32(d0);
                    dst[(size_t)(nc + 1) * KC] = to_tf32(d1);
                }
            }
    } else {
        // V bf16x2 [c][m/2]: pair (nc, nc+1) -> one uint store
        uint* V = g_v + (size_t)b * C * NU + (size_t)(g - 1) * 64 * NU;
#pragma unroll
        for (int am = 0; am < 2; am++)
#pragma unroll
            for (int an = 0; an < 2; an++) {
                int r  = wm + am * 16 + r4;
                int np = (n0 + wn + an * 8 + cc) >> 1;   // pair index
                V[(size_t)r * NU + np]       = pack_bf2(acc[am][an][0] + bsh[r],
                                                        acc[am][an][1] + bsh[r]);
                V[(size_t)(r + 8) * NU + np] = pack_bf2(acc[am][an][2] + bsh[r + 8],
                                                        acc[am][an][3] + bsh[r + 8]);
            }
    }
}

// ---------------- kernel 3: energy via HMMA + exp (unnormalized, bf16 store) ----------------
#define ALD 36
__global__ void attn_mma_kernel() {
    int b  = blockIdx.y;
    int n0 = blockIdx.x * 16;
    int tid  = threadIdx.x;
    int lane = tid & 31, w = tid >> 5;
    int r4 = lane >> 2, q4 = lane & 3;

    __shared__ __align__(16) float Asm[16 * ALD];        // qT tile [16 n][32 k]
    __shared__ __align__(16) float Bs[2][128 * ALD];     // kT chunk [128 m][32 k]
    __shared__ float red[16][8];

    const float* QT = g_qT + (size_t)b * N * KC;
    const float* KT = g_kT + (size_t)b * N * KC;
    uint* P = g_attn + (size_t)b * N * NU;

    if (tid < 128) {
        int row = tid >> 3, seg = tid & 7;
        cp16((uint)__cvta_generic_to_shared(&Asm[row * ALD + seg * 4]),
             QT + (size_t)(n0 + row) * KC + seg * 4);
    }
    {
#pragma unroll
        for (int i = 0; i < 4; i++) {
            int slot = tid + i * 256;
            int rr = slot >> 3, ss = slot & 7;
            cp16((uint)__cvta_generic_to_shared(&Bs[0][rr * ALD + ss * 4]),
                 KT + (size_t)rr * KC + ss * 4);
        }
        asm volatile("cp.async.commit_group;");
    }

    uint a_all[4][4];
    float rs0 = 0.f, rs1 = 0.f;
    const float scale = 0.17677669529663687f;   // 32^-0.5

    for (int ch = 0; ch < 8; ch++) {
        int s = ch & 1;
        if (ch + 1 < 8) {
            int m1 = (ch + 1) * 128;
#pragma unroll
            for (int i = 0; i < 4; i++) {
                int slot = tid + i * 256;
                int rr = slot >> 3, ss = slot & 7;
                cp16((uint)__cvta_generic_to_shared(&Bs[s ^ 1][rr * ALD + ss * 4]),
                     KT + (size_t)(m1 + rr) * KC + ss * 4);
            }
            asm volatile("cp.async.commit_group;");
            asm volatile("cp.async.wait_group 1;");
        } else {
            asm volatile("cp.async.wait_group 0;");
        }
        __syncthreads();

        if (ch == 0) {
            const uint* Au = (const uint*)Asm;
#pragma unroll
            for (int k8 = 0; k8 < 4; k8++) {
                int base = r4 * ALD + k8 * 8 + q4;
                a_all[k8][0] = Au[base];
                a_all[k8][1] = Au[base + 8 * ALD];
                a_all[k8][2] = Au[base + 4];
                a_all[k8][3] = Au[base + 8 * ALD + 4];
            }
        }

        const uint* Bu = (const uint*)Bs[s];
        float acc[2][4];
#pragma unroll
        for (int at = 0; at < 2; at++)
#pragma unroll
            for (int j = 0; j < 4; j++) acc[at][j] = 0.f;

#pragma unroll
        for (int k8 = 0; k8 < 4; k8++) {
            uint bb[2][2];
#pragma unroll
            for (int at = 0; at < 2; at++) {
                int mb = (w * 16 + at * 8 + r4) * ALD + k8 * 8 + q4;
                bb[at][0] = Bu[mb];
                bb[at][1] = Bu[mb + 4];
            }
#pragma unroll
            for (int at = 0; at < 2; at++)
                mma_tf32(acc[at], a_all[k8], bb[at]);
        }

        // exp + bf16x2 store + row-sum accumulation
        int mbase = ch * 128 + w * 16;
#pragma unroll
        for (int at = 0; at < 2; at++) {
            float e0 = fast_expf(acc[at][0] * scale);
            float e1 = fast_expf(acc[at][1] * scale);
            float e2 = fast_expf(acc[at][2] * scale);
            float e3 = fast_expf(acc[at][3] * scale);
            rs0 += e0 + e1;
            rs1 += e2 + e3;
            int pb = ((mbase + at * 8) >> 1) + q4;       // pair index
            P[(size_t)(n0 + r4) * NU + pb]     = pack_bf2(e0, e1);
            P[(size_t)(n0 + r4 + 8) * NU + pb] = pack_bf2(e2, e3);
        }
        __syncthreads();
    }

    rs0 += __shfl_xor_sync(0xFFFFFFFFu, rs0, 1);
    rs0 += __shfl_xor_sync(0xFFFFFFFFu, rs0, 2);
    rs1 += __shfl_xor_sync(0xFFFFFFFFu, rs1, 1);
    rs1 += __shfl_xor_sync(0xFFFFFFFFu, rs1, 2);
    if (q4 == 0) { red[r4][w] = rs0; red[r4 + 8][w] = rs1; }
    __syncthreads();
    if (tid < 16) {
        float s = 0.f;
#pragma unroll
        for (int j = 0; j < 8; j++) s += red[tid][j];
        g_rsum[(size_t)b * N + n0 + tid] = s;
    }
}

// ---------------- kernel 4: out = v @ E^T (scaled by 1/rsum) via bf16 HMMA ----------------
// R9 tiling (64x64, 8 warps of 32x16), operands bf16x2; chunk = 32 pairs = 64 k-elems.
#define GBM 64
#define GBN 64
#define GBKP 32            // pairs per chunk
#define LDP 36             // uint stride per row (pairs + pad)
#define NCHUNKB (NU / GBKP)  // 16
__global__ __launch_bounds__(256) void out_gemm_kernel() {
    __shared__ __align__(16) uint Vs[2][GBM * LDP];
    __shared__ __align__(16) uint Ps[2][GBN * LDP];

    int b  = blockIdx.z;
    int c0 = blockIdx.y * GBM;
    int n0 = blockIdx.x * GBN;

    int tid  = threadIdx.x;      // 0..255
    int lane = tid & 31, wid = tid >> 5;
    int wm = (wid & 1) * 32;
    int wn = (wid >> 1) * 16;

    const uint* V = g_v    + (size_t)b * C * NU;
    const uint* P = g_attn + (size_t)b * N * NU;

    // copy slots: 64 rows x 8 segs(4 uints) = 512 per array; 256 threads x 2 iters
    int crow = tid >> 3;          // 0..31
    int cseg = (tid & 7) * 4;

    float acc[2][2][4];
#pragma unroll
    for (int am = 0; am < 2; am++)
#pragma unroll
        for (int an = 0; an < 2; an++)
#pragma unroll
            for (int j = 0; j < 4; j++) acc[am][an][j] = 0.f;

    int r4 = lane >> 2, q4 = lane & 3;

    // stage-0 prefetch
    {
#pragma unroll
        for (int i = 0; i < 2; i++) {
            int row = crow + i * 32;
            cp16((uint)__cvta_generic_to_shared(&Vs[0][row * LDP + cseg]),
                 V + (size_t)(c0 + row) * NU + cseg);
            cp16((uint)__cvta_generic_to_shared(&Ps[0][row * LDP + cseg]),
                 P + (size_t)(n0 + row) * NU + cseg);
        }
        asm volatile("cp.async.commit_group;");
    }

    for (int ch = 0; ch < NCHUNKB; ch++) {
        int s = ch & 1;
        if (ch + 1 < NCHUNKB) {
            int m1 = (ch + 1) * GBKP;
#pragma unroll
            for (int i = 0; i < 2; i++) {
                int row = crow + i * 32;
                cp16((uint)__cvta_generic_to_shared(&Vs[s ^ 1][row * LDP + cseg]),
                     V + (size_t)(c0 + row) * NU + m1 + cseg);
                cp16((uint)__cvta_generic_to_shared(&Ps[s ^ 1][row * LDP + cseg]),
                     P + (size_t)(n0 + row) * NU + m1 + cseg);
            }
            asm volatile("cp.async.commit_group;");
            asm volatile("cp.async.wait_group 1;");
        } else {
            asm volatile("cp.async.wait_group 0;");
        }
        __syncthreads();

        const uint* Vss = Vs[s];
        const uint* Pss = Ps[s];
#pragma unroll
        for (int k8 = 0; k8 < GBKP; k8 += 8) {   // 4 mma-steps of k16 each
            uint a[2][4], bb[2][2];
#pragma unroll
            for (int am = 0; am < 2; am++) {
                int base = (wm + am * 16 + r4) * LDP + k8 + q4;
                a[am][0] = Vss[base];
                a[am][1] = Vss[base + 8 * LDP];
                a[am][2] = Vss[base + 4];
                a[am][3] = Vss[base + 8 * LDP + 4];
            }
#pragma unroll
            for (int an = 0; an < 2; an++) {
                int base = (wn + an * 8 + r4) * LDP + k8 + q4;
                bb[an][0] = Pss[base];
                bb[an][1] = Pss[base + 4];
            }
#pragma unroll
            for (int am = 0; am < 2; am++)
#pragma unroll
                for (int an = 0; an < 2; an++)
                    mma_bf16(acc[am][an], a[am], bb[an]);
        }
        __syncthreads();
    }

    float* O = g_out + (size_t)b * C * N;
    const float* RS = g_rsum + (size_t)b * N;
    int cc = (lane & 3) * 2;
    float inv[2][2];
#pragma unroll
    for (int an = 0; an < 2; an++) {
        int nc = n0 + wn + an * 8 + cc;
        inv[an][0] = 1.0f / RS[nc];
        inv[an][1] = 1.0f / RS[nc + 1];
    }
#pragma unroll
    for (int am = 0; am < 2; am++)
#pragma unroll
        for (int an = 0; an < 2; an++) {
            int cr = c0 + wm + am * 16 + r4;
            int ncol = n0 + wn + an * 8 + cc;
            float2 lo; lo.x = acc[am][an][0] * inv[an][0]; lo.y = acc[am][an][1] * inv[an][1];
            float2 hi; hi.x = acc[am][an][2] * inv[an][0]; hi.y = acc[am][an][3] * inv[an][1];
            *(float2*)(O + (size_t)cr * N + ncol)       = lo;
            *(float2*)(O + (size_t)(cr + 8) * N + ncol) = hi;
        }
}

// ---------------- kernel 5: nearest 8x upsample + residual ----------------
__global__ void upsample_add_kernel(const float* __restrict__ f, float* __restrict__ out) {
    size_t idx = (size_t)blockIdx.x * blockDim.x + threadIdx.x;  // over B*C*H*W/4
    int w4 = (int)(idx & 63);
    int h  = (int)((idx >> 6) & 255);
    size_t bc = idx >> 14;
    int hp = h >> 3;
    int wp = w4 >> 1;
    float s = g_out[bc * N + (size_t)hp * WP + wp];
    float4 a = ((const float4*)f)[idx];
    a.x += s; a.y += s; a.z += s; a.w += s;
    ((float4*)out)[idx] = a;
}

// ---------------- launch ----------------
extern "C" void kernel_launch(void* const* d_in, const int* in_sizes, int n_in,
                              void* d_out, int out_size) {
    const float* f  = (const float*)d_in[0];
    const float* qw = (const float*)d_in[1];
    const float* qb = (const float*)d_in[2];
    const float* kw = (const float*)d_in[3];
    const float* kb = (const float*)d_in[4];
    const float* vw = (const float*)d_in[5];
    const float* vb = (const float*)d_in[6];
    float* out = (float*)d_out;

    avgpool_kernel<<<(BATCH * C * N) / 256, 256>>>(f);
    qkv_mma_kernel<<<dim3(N / 64, 5, BATCH), 256>>>(qw, qb, kw, kb, vw, vb);
    attn_mma_kernel<<<dim3(N / 16, BATCH), 256>>>();
    out_gemm_kernel<<<dim3(N / GBN, C / GBM, BATCH), 256>>>();
    upsample_add_kernel<<<(BATCH * C * H * (W / 4)) / 256, 256>>>(f, out);
}

// round 14
// speedup vs baseline: 1.3117x; 1.0225x over previous
#include <cuda_runtime.h>
#include <cuda_bf16.h>

#define BATCH 4
#define C 256
#define H 256
#define W 256
#define S 8
#define HP 32
#define WP 32
#define N 1024     // HP*WP tokens
#define KC 32      // key channels
#define NU (N / 2) // bf16 pairs per token row
#define CP (C / 2) // channel pairs
#define KU (KC / 2)

typedef unsigned int uint;

// ---------------- device scratch (no allocs allowed) ----------------
__device__ uint  g_wcat[320 * CP];              // [qw;kw;vw] bf16x2 pairs along c
__device__ uint  g_xf2[BATCH * CP * N];         // pooled features bf16x2 [b][cpair][n]
__device__ uint  g_qT2[BATCH * N * KU];         // q bf16x2 [b][n][kpair]
__device__ uint  g_kT2[BATCH * N * KU];         // k bf16x2 [b][m][kpair]
__device__ uint  g_v[BATCH * C * NU];           // v bf16x2 [b][c][m/2]
__device__ uint  g_attn[BATCH * N * NU];        // exp(energy) bf16x2 [b][n][m/2]
__device__ float g_rsum[BATCH * N];             // softmax row sums
__device__ float g_out[BATCH * C * N];          // attn output [b][c][n]

__device__ __forceinline__ uint pack_bf2(float lo, float hi) {
    __nv_bfloat162 t = __floats2bfloat162_rn(lo, hi);
    return *(uint*)&t;
}

__device__ __forceinline__ void mma_bf16(float* d, const uint* a, const uint* b) {
    asm volatile(
        "mma.sync.aligned.m16n8k16.row.col.f32.bf16.bf16.f32 "
        "{%0,%1,%2,%3}, {%4,%5,%6,%7}, {%8,%9}, {%0,%1,%2,%3};"
        : "+f"(d[0]), "+f"(d[1]), "+f"(d[2]), "+f"(d[3])
        : "r"(a[0]), "r"(a[1]), "r"(a[2]), "r"(a[3]), "r"(b[0]), "r"(b[1]));
}

__device__ __forceinline__ void cp16(uint smem_addr, const void* gptr) {
    asm volatile("cp.async.ca.shared.global [%0], [%1], 16;"
                 :: "r"(smem_addr), "l"(gptr));
}

// FMA-pipe exp
__device__ __forceinline__ float fast_expf(float x) {
    x = fmaxf(x, -80.0f);
    float y = x * 1.4426950408889634f;
    float z = y + 12582912.0f;
    int   e = __float_as_int(z);
    float n = z - 12582912.0f;
    float f = y - n;
    float p = 0.0013333558146428443f;
    p = fmaf(p, f, 0.009618129107628477f);
    p = fmaf(p, f, 0.05550410866482158f);
    p = fmaf(p, f, 0.2402265069591007f);
    p = fmaf(p, f, 0.6931471805599453f);
    p = fmaf(p, f, 1.0f);
    return __int_as_float(__float_as_int(p) + (e << 23));
}

// ---------------- kernel 0: weight prep (f32 -> bf16x2) ----------------
__global__ void prep_w_kernel(const float* __restrict__ qw, const float* __restrict__ kw,
                              const float* __restrict__ vw) {
    int idx = blockIdx.x * 256 + threadIdx.x;   // 320*128 = 40960
    int row = idx >> 7, p = idx & (CP - 1);
    const float* src;
    if (row < 32)      src = qw + (size_t)row * C;
    else if (row < 64) src = kw + (size_t)(row - 32) * C;
    else               src = vw + (size_t)(row - 64) * C;
    float2 v = *(const float2*)(src + 2 * p);
    g_wcat[idx] = pack_bf2(v.x, v.y);
}

// ---------------- kernel 1: 8x8 avg pool -> bf16x2 channel pairs ----------------
__global__ void avgpool_kernel(const float* __restrict__ f) {
    int idx = blockIdx.x * blockDim.x + threadIdx.x;   // over BATCH*CP*N
    int n  = idx & (N - 1);
    int bp = idx >> 10;            // b*CP + p
    int wp = n & (WP - 1);
    int hp = n >> 5;
    const float* src0 = f + (((size_t)bp * 2) * H + (size_t)hp * S) * W + (size_t)wp * S;
    const float* src1 = src0 + (size_t)H * W;
    float s0 = 0.f, s1 = 0.f;
#pragma unroll
    for (int r = 0; r < S; r++) {
        float4 a = *(const float4*)(src0 + (size_t)r * W);
        float4 b = *(const float4*)(src0 + (size_t)r * W + 4);
        s0 += a.x + a.y + a.z + a.w + b.x + b.y + b.z + b.w;
        float4 c = *(const float4*)(src1 + (size_t)r * W);
        float4 d = *(const float4*)(src1 + (size_t)r * W + 4);
        s1 += c.x + c.y + c.z + c.w + d.x + d.y + d.z + d.w;
    }
    g_xf2[idx] = pack_bf2(s0 * (1.f / 64.f), s1 * (1.f / 64.f));
}

// ---------------- kernel 2: q/k/v via bf16 HMMA ----------------
// group 0: rows 0..31 = q, 32..63 = k -> g_qT2/g_kT2 [token][kpair] (bf16 scalar scatters)
// group 1..4: v rows -> g_v [c][m/2]
#define QLDA 20    // 16 pair-cols + 4 pad
#define QLDB 72    // 64 n + 8 pad
__global__ void qkv_mma_kernel(const float* __restrict__ qb, const float* __restrict__ kb,
                               const float* __restrict__ vb) {
    int b  = blockIdx.z;
    int g  = blockIdx.y;
    int n0 = blockIdx.x * 64;

    __shared__ __align__(16) uint As[2][64 * QLDA];   // A[m=64][16 kpairs]
    __shared__ __align__(16) uint Bs[2][16 * QLDB];   // B[16 kpairs][n=64]
    __shared__ float bsh[64];

    int tid  = threadIdx.x;
    int lane = tid & 31, wid = tid >> 5;
    int wm = (wid & 1) * 32;
    int wn = (wid >> 1) * 16;
    int r4 = lane >> 2, q4 = lane & 3;

    int arow = tid >> 2, aseg = tid & 3;      // A: 64 rows x 4 segs
    int brow = tid >> 4, bseg = tid & 15;     // B: 16 rows x 16 segs

    const uint* wsrc = g_wcat + (size_t)(g * 64 + arow) * CP;
    const uint* xfb  = g_xf2 + (size_t)b * CP * N;

    if (tid < 64) {
        float bv;
        if (g == 0) bv = (tid < 32) ? qb[tid] : kb[tid - 32];
        else        bv = vb[(g - 1) * 64 + tid];
        bsh[tid] = bv;
    }

    float acc[2][2][4];
#pragma unroll
    for (int am = 0; am < 2; am++)
#pragma unroll
        for (int an = 0; an < 2; an++)
#pragma unroll
            for (int j = 0; j < 4; j++) acc[am][an][j] = 0.f;

    // prefetch chunk 0 (pairs [0,16))
    {
        cp16((uint)__cvta_generic_to_shared(&As[0][arow * QLDA + aseg * 4]), wsrc + aseg * 4);
        cp16((uint)__cvta_generic_to_shared(&Bs[0][brow * QLDB + bseg * 4]),
             xfb + (size_t)brow * N + n0 + bseg * 4);
        asm volatile("cp.async.commit_group;");
    }

    for (int ch = 0; ch < 8; ch++) {          // 8 chunks x 16 pairs = 128 pairs = 256 c
        int s = ch & 1;
        if (ch + 1 < 8) {
            int c1p = (ch + 1) * 16;
            cp16((uint)__cvta_generic_to_shared(&As[s ^ 1][arow * QLDA + aseg * 4]),
                 wsrc + c1p + aseg * 4);
            cp16((uint)__cvta_generic_to_shared(&Bs[s ^ 1][brow * QLDB + bseg * 4]),
                 xfb + (size_t)(c1p + brow) * N + n0 + bseg * 4);
            asm volatile("cp.async.commit_group;");
            asm volatile("cp.async.wait_group 1;");
        } else {
            asm volatile("cp.async.wait_group 0;");
        }
        __syncthreads();

        const uint* Ass = As[s];
        const uint* Bss = Bs[s];
#pragma unroll
        for (int st = 0; st < 2; st++) {      // 2 x k16
            uint a[2][4], bb[2][2];
#pragma unroll
            for (int am = 0; am < 2; am++) {
                int base = (wm + am * 16 + r4) * QLDA + st * 8 + q4;
                a[am][0] = Ass[base];
                a[am][1] = Ass[base + 8 * QLDA];
                a[am][2] = Ass[base + 4];
                a[am][3] = Ass[base + 8 * QLDA + 4];
            }
#pragma unroll
            for (int an = 0; an < 2; an++) {
                int nb = wn + an * 8 + r4;
                bb[an][0] = Bss[(st * 8 + q4) * QLDB + nb];
                bb[an][1] = Bss[(st * 8 + q4 + 4) * QLDB + nb];
            }
#pragma unroll
            for (int am = 0; am < 2; am++)
#pragma unroll
                for (int an = 0; an < 2; an++)
                    mma_bf16(acc[am][an], a[am], bb[an]);
        }
        __syncthreads();
    }

    int cc = (lane & 3) * 2;
    if (g == 0) {
        __nv_bfloat16* QT = (__nv_bfloat16*)g_qT2 + (size_t)b * N * KC;
        __nv_bfloat16* KT = (__nv_bfloat16*)g_kT2 + (size_t)b * N * KC;
#pragma unroll
        for (int am = 0; am < 2; am++)
#pragma unroll
            for (int an = 0; an < 2; an++) {
                int r  = wm + am * 16 + r4;
                int nc = n0 + wn + an * 8 + cc;
#pragma unroll
                for (int dr = 0; dr < 2; dr++) {
                    int rr = r + dr * 8;
                    float d0 = acc[am][an][dr * 2 + 0] + bsh[rr];
                    float d1 = acc[am][an][dr * 2 + 1] + bsh[rr];
                    int ch_ = (rr < 32) ? rr : rr - 32;
                    __nv_bfloat16* dst = (rr < 32) ? QT : KT;
                    dst[(size_t)nc * KC + ch_]       = __float2bfloat16(d0);
                    dst[(size_t)(nc + 1) * KC + ch_] = __float2bfloat16(d1);
                }
            }
    } else {
        uint* V = g_v + (size_t)b * C * NU + (size_t)(g - 1) * 64 * NU;
#pragma unroll
        for (int am = 0; am < 2; am++)
#pragma unroll
            for (int an = 0; an < 2; an++) {
                int r  = wm + am * 16 + r4;
                int np = (n0 + wn + an * 8 + cc) >> 1;
                V[(size_t)r * NU + np]       = pack_bf2(acc[am][an][0] + bsh[r],
                                                        acc[am][an][1] + bsh[r]);
                V[(size_t)(r + 8) * NU + np] = pack_bf2(acc[am][an][2] + bsh[r + 8],
                                                        acc[am][an][3] + bsh[r + 8]);
            }
    }
}

// ---------------- kernel 3: energy via bf16 HMMA + exp + row sums ----------------
#define ALD 20   // 16 kpairs + 4 pad
__global__ void attn_mma_kernel() {
    int b  = blockIdx.y;
    int n0 = blockIdx.x * 16;
    int tid  = threadIdx.x;
    int lane = tid & 31, w = tid >> 5;
    int r4 = lane >> 2, q4 = lane & 3;

    __shared__ __align__(16) uint Asm[16 * ALD];        // qT tile [16 n][16 kpairs]
    __shared__ __align__(16) uint Bs[2][128 * ALD];     // kT chunk [128 m][16 kpairs]
    __shared__ float red[16][8];

    const uint* QT = g_qT2 + (size_t)b * N * KU;
    const uint* KT = g_kT2 + (size_t)b * N * KU;
    uint* P = g_attn + (size_t)b * N * NU;

    if (tid < 64) {
        int row = tid >> 2, seg = tid & 3;
        cp16((uint)__cvta_generic_to_shared(&Asm[row * ALD + seg * 4]),
             QT + (size_t)(n0 + row) * KU + seg * 4);
    }
    {
#pragma unroll
        for (int i = 0; i < 2; i++) {
            int slot = tid + i * 256;        // 128 rows x 4 segs = 512
            int rr = slot >> 2, ss = slot & 3;
            cp16((uint)__cvta_generic_to_shared(&Bs[0][rr * ALD + ss * 4]),
                 KT + (size_t)rr * KU + ss * 4);
        }
        asm volatile("cp.async.commit_group;");
    }

    uint a_all[2][4];
    float rs0 = 0.f, rs1 = 0.f;
    const float scale = 0.17677669529663687f;   // 32^-0.5

    for (int ch = 0; ch < 8; ch++) {
        int s = ch & 1;
        if (ch + 1 < 8) {
            int m1 = (ch + 1) * 128;
#pragma unroll
            for (int i = 0; i < 2; i++) {
                int slot = tid + i * 256;
                int rr = slot >> 2, ss = slot & 3;
                cp16((uint)__cvta_generic_to_shared(&Bs[s ^ 1][rr * ALD + ss * 4]),
                     KT + (size_t)(m1 + rr) * KU + ss * 4);
            }
            asm volatile("cp.async.commit_group;");
            asm volatile("cp.async.wait_group 1;");
        } else {
            asm volatile("cp.async.wait_group 0;");
        }
        __syncthreads();

        if (ch == 0) {
#pragma unroll
            for (int st = 0; st < 2; st++) {
                int base = r4 * ALD + st * 8 + q4;
                a_all[st][0] = Asm[base];
                a_all[st][1] = Asm[base + 8 * ALD];
                a_all[st][2] = Asm[base + 4];
                a_all[st][3] = Asm[base + 8 * ALD + 4];
            }
        }

        const uint* Bu = Bs[s];
        float acc[2][4];
#pragma unroll
        for (int at = 0; at < 2; at++)
#pragma unroll
            for (int j = 0; j < 4; j++) acc[at][j] = 0.f;

#pragma unroll
        for (int st = 0; st < 2; st++) {
            uint bb[2][2];
#pragma unroll
            for (int at = 0; at < 2; at++) {
                int mb = (w * 16 + at * 8 + r4) * ALD + st * 8 + q4;
                bb[at][0] = Bu[mb];
                bb[at][1] = Bu[mb + 4];
            }
#pragma unroll
            for (int at = 0; at < 2; at++)
                mma_bf16(acc[at], a_all[st], bb[at]);
        }

        int mbase = ch * 128 + w * 16;
#pragma unroll
        for (int at = 0; at < 2; at++) {
            float e0 = fast_expf(acc[at][0] * scale);
            float e1 = fast_expf(acc[at][1] * scale);
            float e2 = fast_expf(acc[at][2] * scale);
            float e3 = fast_expf(acc[at][3] * scale);
            rs0 += e0 + e1;
            rs1 += e2 + e3;
            int pb = ((mbase + at * 8) >> 1) + q4;
            P[(size_t)(n0 + r4) * NU + pb]     = pack_bf2(e0, e1);
            P[(size_t)(n0 + r4 + 8) * NU + pb] = pack_bf2(e2, e3);
        }
        __syncthreads();
    }

    rs0 += __shfl_xor_sync(0xFFFFFFFFu, rs0, 1);
    rs0 += __shfl_xor_sync(0xFFFFFFFFu, rs0, 2);
    rs1 += __shfl_xor_sync(0xFFFFFFFFu, rs1, 1);
    rs1 += __shfl_xor_sync(0xFFFFFFFFu, rs1, 2);
    if (q4 == 0) { red[r4][w] = rs0; red[r4 + 8][w] = rs1; }
    __syncthreads();
    if (tid < 16) {
        float s = 0.f;
#pragma unroll
        for (int j = 0; j < 8; j++) s += red[tid][j];
        g_rsum[(size_t)b * N + n0 + tid] = s;
    }
}

// ---------------- kernel 4: out = v @ E^T (scaled by 1/rsum) via bf16 HMMA ----------------
#define GBM 64
#define GBN 64
#define GBKP 32
#define LDP 36
#define NCHUNKB (NU / GBKP)
__global__ __launch_bounds__(256) void out_gemm_kernel() {
    __shared__ __align__(16) uint Vs[2][GBM * LDP];
    __shared__ __align__(16) uint Ps[2][GBN * LDP];

    int b  = blockIdx.z;
    int c0 = blockIdx.y * GBM;
    int n0 = blockIdx.x * GBN;

    int tid  = threadIdx.x;
    int lane = tid & 31, wid = tid >> 5;
    int wm = (wid & 1) * 32;
    int wn = (wid >> 1) * 16;

    const uint* V = g_v    + (size_t)b * C * NU;
    const uint* P = g_attn + (size_t)b * N * NU;

    int crow = tid >> 3;
    int cseg = (tid & 7) * 4;

    float acc[2][2][4];
#pragma unroll
    for (int am = 0; am < 2; am++)
#pragma unroll
        for (int an = 0; an < 2; an++)
#pragma unroll
            for (int j = 0; j < 4; j++) acc[am][an][j] = 0.f;

    int r4 = lane >> 2, q4 = lane & 3;

    {
#pragma unroll
        for (int i = 0; i < 2; i++) {
            int row = crow + i * 32;
            cp16((uint)__cvta_generic_to_shared(&Vs[0][row * LDP + cseg]),
                 V + (size_t)(c0 + row) * NU + cseg);
            cp16((uint)__cvta_generic_to_shared(&Ps[0][row * LDP + cseg]),
                 P + (size_t)(n0 + row) * NU + cseg);
        }
        asm volatile("cp.async.commit_group;");
    }

    for (int ch = 0; ch < NCHUNKB; ch++) {
        int s = ch & 1;
        if (ch + 1 < NCHUNKB) {
            int m1 = (ch + 1) * GBKP;
#pragma unroll
            for (int i = 0; i < 2; i++) {
                int row = crow + i * 32;
                cp16((uint)__cvta_generic_to_shared(&Vs[s ^ 1][row * LDP + cseg]),
                     V + (size_t)(c0 + row) * NU + m1 + cseg);
                cp16((uint)__cvta_generic_to_shared(&Ps[s ^ 1][row * LDP + cseg]),
                     P + (size_t)(n0 + row) * NU + m1 + cseg);
            }
            asm volatile("cp.async.commit_group;");
            asm volatile("cp.async.wait_group 1;");
        } else {
            asm volatile("cp.async.wait_group 0;");
        }
        __syncthreads();

        const uint* Vss = Vs[s];
        const uint* Pss = Ps[s];
#pragma unroll
        for (int k8 = 0; k8 < GBKP; k8 += 8) {
            uint a[2][4], bb[2][2];
#pragma unroll
            for (int am = 0; am < 2; am++) {
                int base = (wm + am * 16 + r4) * LDP + k8 + q4;
                a[am][0] = Vss[base];
                a[am][1] = Vss[base + 8 * LDP];
                a[am][2] = Vss[base + 4];
                a[am][3] = Vss[base + 8 * LDP + 4];
            }
#pragma unroll
            for (int an = 0; an < 2; an++) {
                int base = (wn + an * 8 + r4) * LDP + k8 + q4;
                bb[an][0] = Pss[base];
                bb[an][1] = Pss[base + 4];
            }
#pragma unroll
            for (int am = 0; am < 2; am++)
#pragma unroll
                for (int an = 0; an < 2; an++)
                    mma_bf16(acc[am][an], a[am], bb[an]);
        }
        __syncthreads();
    }

    float* O = g_out + (size_t)b * C * N;
    const float* RS = g_rsum + (size_t)b * N;
    int cc = (lane & 3) * 2;
    float inv[2][2];
#pragma unroll
    for (int an = 0; an < 2; an++) {
        int nc = n0 + wn + an * 8 + cc;
        inv[an][0] = 1.0f / RS[nc];
        inv[an][1] = 1.0f / RS[nc + 1];
    }
#pragma unroll
    for (int am = 0; am < 2; am++)
#pragma unroll
        for (int an = 0; an < 2; an++) {
            int cr = c0 + wm + am * 16 + r4;
            int ncol = n0 + wn + an * 8 + cc;
            float2 lo; lo.x = acc[am][an][0] * inv[an][0]; lo.y = acc[am][an][1] * inv[an][1];
            float2 hi; hi.x = acc[am][an][2] * inv[an][0]; hi.y = acc[am][an][3] * inv[an][1];
            *(float2*)(O + (size_t)cr * N + ncol)       = lo;
            *(float2*)(O + (size_t)(cr + 8) * N + ncol) = hi;
        }
}

// ---------------- kernel 5: nearest 8x upsample + residual ----------------
__global__ void upsample_add_kernel(const float* __restrict__ f, float* __restrict__ out) {
    size_t idx = (size_t)blockIdx.x * blockDim.x + threadIdx.x;
    int w4 = (int)(idx & 63);
    int h  = (int)((idx >> 6) & 255);
    size_t bc = idx >> 14;
    int hp = h >> 3;
    int wp = w4 >> 1;
    float s = g_out[bc * N + (size_t)hp * WP + wp];
    float4 a = ((const float4*)f)[idx];
    a.x += s; a.y += s; a.z += s; a.w += s;
    ((float4*)out)[idx] = a;
}

// ---------------- launch ----------------
extern "C" void kernel_launch(void* const* d_in, const int* in_sizes, int n_in,
                              void* d_out, int out_size) {
    const float* f  = (const float*)d_in[0];
    const float* qw = (const float*)d_in[1];
    const float* qb = (const float*)d_in[2];
    const float* kw = (const float*)d_in[3];
    const float* kb = (const float*)d_in[4];
    const float* vw = (const float*)d_in[5];
    const float* vb = (const float*)d_in[6];
    float* out = (float*)d_out;

    prep_w_kernel<<<160, 256>>>(qw, kw, vw);
    avgpool_kernel<<<(BATCH * CP * N) / 256, 256>>>(f);
    qkv_mma_kernel<<<dim3(N / 64, 5, BATCH), 256>>>(qb, kb, vb);
    attn_mma_kernel<<<dim3(N / 16, BATCH), 256>>>();
    out_gemm_kernel<<<dim3(N / GBN, C / GBM, BATCH), 256>>>();
    upsample_add_kernel<<<(BATCH * C * H * (W / 4)) / 256, 256>>>(f, out);
}

// round 15
// speedup vs baseline: 1.3314x; 1.0150x over previous
#include <cuda_runtime.h>
#include <cuda_bf16.h>

#define BATCH 4
#define C 256
#define H 256
#define W 256
#define S 8
#define HP 32
#define WP 32
#define N 1024     // HP*WP tokens
#define KC 32      // key channels
#define NU (N / 2) // bf16 pairs per token row
#define CP (C / 2) // channel pairs
#define KU (KC / 2)

typedef unsigned int uint;

// ---------------- device scratch (no allocs allowed) ----------------
__device__ uint  g_wcat[320 * CP];              // [qw;kw;vw] bf16x2 pairs along c
__device__ uint  g_xf2[BATCH * CP * N];         // pooled features bf16x2 [b][cpair][n]
__device__ uint  g_qT2[BATCH * N * KU];         // q bf16x2 [b][n][kpair]
__device__ uint  g_kT2[BATCH * N * KU];         // k bf16x2 [b][m][kpair]
__device__ uint  g_v[BATCH * C * NU];           // v bf16x2 [b][c][m/2]
__device__ float g_out[BATCH * C * N];          // attn output [b][c][n]

__device__ __forceinline__ uint pack_bf2(float lo, float hi) {
    __nv_bfloat162 t = __floats2bfloat162_rn(lo, hi);
    return *(uint*)&t;
}

__device__ __forceinline__ void mma_bf16(float* d, const uint* a, const uint* b) {
    asm volatile(
        "mma.sync.aligned.m16n8k16.row.col.f32.bf16.bf16.f32 "
        "{%0,%1,%2,%3}, {%4,%5,%6,%7}, {%8,%9}, {%0,%1,%2,%3};"
        : "+f"(d[0]), "+f"(d[1]), "+f"(d[2]), "+f"(d[3])
        : "r"(a[0]), "r"(a[1]), "r"(a[2]), "r"(a[3]), "r"(b[0]), "r"(b[1]));
}

__device__ __forceinline__ void cp16(uint smem_addr, const void* gptr) {
    asm volatile("cp.async.ca.shared.global [%0], [%1], 16;"
                 :: "r"(smem_addr), "l"(gptr));
}

// FMA-pipe exp
__device__ __forceinline__ float fast_expf(float x) {
    x = fmaxf(x, -80.0f);
    float y = x * 1.4426950408889634f;
    float z = y + 12582912.0f;
    int   e = __float_as_int(z);
    float n = z - 12582912.0f;
    float f = y - n;
    float p = 0.0013333558146428443f;
    p = fmaf(p, f, 0.009618129107628477f);
    p = fmaf(p, f, 0.05550410866482158f);
    p = fmaf(p, f, 0.2402265069591007f);
    p = fmaf(p, f, 0.6931471805599453f);
    p = fmaf(p, f, 1.0f);
    return __int_as_float(__float_as_int(p) + (e << 23));
}

// ---------------- kernel 0: weight prep (f32 -> bf16x2) ----------------
__global__ void prep_w_kernel(const float* __restrict__ qw, const float* __restrict__ kw,
                              const float* __restrict__ vw) {
    int idx = blockIdx.x * 256 + threadIdx.x;   // 320*128 = 40960
    int row = idx >> 7, p = idx & (CP - 1);
    const float* src;
    if (row < 32)      src = qw + (size_t)row * C;
    else if (row < 64) src = kw + (size_t)(row - 32) * C;
    else               src = vw + (size_t)(row - 64) * C;
    float2 v = *(const float2*)(src + 2 * p);
    g_wcat[idx] = pack_bf2(v.x, v.y);
}

// ---------------- kernel 1: 8x8 avg pool -> bf16x2 channel pairs ----------------
__global__ void avgpool_kernel(const float* __restrict__ f) {
    int idx = blockIdx.x * blockDim.x + threadIdx.x;   // over BATCH*CP*N
    int n  = idx & (N - 1);
    int bp = idx >> 10;
    int wp = n & (WP - 1);
    int hp = n >> 5;
    const float* src0 = f + (((size_t)bp * 2) * H + (size_t)hp * S) * W + (size_t)wp * S;
    const float* src1 = src0 + (size_t)H * W;
    float s0 = 0.f, s1 = 0.f;
#pragma unroll
    for (int r = 0; r < S; r++) {
        float4 a = *(const float4*)(src0 + (size_t)r * W);
        float4 b = *(const float4*)(src0 + (size_t)r * W + 4);
        s0 += a.x + a.y + a.z + a.w + b.x + b.y + b.z + b.w;
        float4 c = *(const float4*)(src1 + (size_t)r * W);
        float4 d = *(const float4*)(src1 + (size_t)r * W + 4);
        s1 += c.x + c.y + c.z + c.w + d.x + d.y + d.z + d.w;
    }
    g_xf2[idx] = pack_bf2(s0 * (1.f / 64.f), s1 * (1.f / 64.f));
}

// ---------------- kernel 2: q/k/v via bf16 HMMA (unchanged from R14) ----------------
#define QLDA 20
#define QLDB 72
__global__ void qkv_mma_kernel(const float* __restrict__ qb, const float* __restrict__ kb,
                               const float* __restrict__ vb) {
    int b  = blockIdx.z;
    int g  = blockIdx.y;
    int n0 = blockIdx.x * 64;

    __shared__ __align__(16) uint As[2][64 * QLDA];
    __shared__ __align__(16) uint Bs[2][16 * QLDB];
    __shared__ float bsh[64];

    int tid  = threadIdx.x;
    int lane = tid & 31, wid = tid >> 5;
    int wm = (wid & 1) * 32;
    int wn = (wid >> 1) * 16;
    int r4 = lane >> 2, q4 = lane & 3;

    int arow = tid >> 2, aseg = tid & 3;
    int brow = tid >> 4, bseg = tid & 15;

    const uint* wsrc = g_wcat + (size_t)(g * 64 + arow) * CP;
    const uint* xfb  = g_xf2 + (size_t)b * CP * N;

    if (tid < 64) {
        float bv;
        if (g == 0) bv = (tid < 32) ? qb[tid] : kb[tid - 32];
        else        bv = vb[(g - 1) * 64 + tid];
        bsh[tid] = bv;
    }

    float acc[2][2][4];
#pragma unroll
    for (int am = 0; am < 2; am++)
#pragma unroll
        for (int an = 0; an < 2; an++)
#pragma unroll
            for (int j = 0; j < 4; j++) acc[am][an][j] = 0.f;

    {
        cp16((uint)__cvta_generic_to_shared(&As[0][arow * QLDA + aseg * 4]), wsrc + aseg * 4);
        cp16((uint)__cvta_generic_to_shared(&Bs[0][brow * QLDB + bseg * 4]),
             xfb + (size_t)brow * N + n0 + bseg * 4);
        asm volatile("cp.async.commit_group;");
    }

    for (int ch = 0; ch < 8; ch++) {
        int s = ch & 1;
        if (ch + 1 < 8) {
            int c1p = (ch + 1) * 16;
            cp16((uint)__cvta_generic_to_shared(&As[s ^ 1][arow * QLDA + aseg * 4]),
                 wsrc + c1p + aseg * 4);
            cp16((uint)__cvta_generic_to_shared(&Bs[s ^ 1][brow * QLDB + bseg * 4]),
                 xfb + (size_t)(c1p + brow) * N + n0 + bseg * 4);
            asm volatile("cp.async.commit_group;");
            asm volatile("cp.async.wait_group 1;");
        } else {
            asm volatile("cp.async.wait_group 0;");
        }
        __syncthreads();

        const uint* Ass = As[s];
        const uint* Bss = Bs[s];
#pragma unroll
        for (int st = 0; st < 2; st++) {
            uint a[2][4], bb[2][2];
#pragma unroll
            for (int am = 0; am < 2; am++) {
                int base = (wm + am * 16 + r4) * QLDA + st * 8 + q4;
                a[am][0] = Ass[base];
                a[am][1] = Ass[base + 8 * QLDA];
                a[am][2] = Ass[base + 4];
                a[am][3] = Ass[base + 8 * QLDA + 4];
            }
#pragma unroll
            for (int an = 0; an < 2; an++) {
                int nb = wn + an * 8 + r4;
                bb[an][0] = Bss[(st * 8 + q4) * QLDB + nb];
                bb[an][1] = Bss[(st * 8 + q4 + 4) * QLDB + nb];
            }
#pragma unroll
            for (int am = 0; am < 2; am++)
#pragma unroll
                for (int an = 0; an < 2; an++)
                    mma_bf16(acc[am][an], a[am], bb[an]);
        }
        __syncthreads();
    }

    int cc = (lane & 3) * 2;
    if (g == 0) {
        __nv_bfloat16* QT = (__nv_bfloat16*)g_qT2 + (size_t)b * N * KC;
        __nv_bfloat16* KT = (__nv_bfloat16*)g_kT2 + (size_t)b * N * KC;
#pragma unroll
        for (int am = 0; am < 2; am++)
#pragma unroll
            for (int an = 0; an < 2; an++) {
                int r  = wm + am * 16 + r4;
                int nc = n0 + wn + an * 8 + cc;
#pragma unroll
                for (int dr = 0; dr < 2; dr++) {
                    int rr = r + dr * 8;
                    float d0 = acc[am][an][dr * 2 + 0] + bsh[rr];
                    float d1 = acc[am][an][dr * 2 + 1] + bsh[rr];
                    int ch_ = (rr < 32) ? rr : rr - 32;
                    __nv_bfloat16* dst = (rr < 32) ? QT : KT;
                    dst[(size_t)nc * KC + ch_]       = __float2bfloat16(d0);
                    dst[(size_t)(nc + 1) * KC + ch_] = __float2bfloat16(d1);
                }
            }
    } else {
        uint* V = g_v + (size_t)b * C * NU + (size_t)(g - 1) * 64 * NU;
#pragma unroll
        for (int am = 0; am < 2; am++)
#pragma unroll
            for (int an = 0; an < 2; an++) {
                int r  = wm + am * 16 + r4;
                int np = (n0 + wn + an * 8 + cc) >> 1;
                V[(size_t)r * NU + np]       = pack_bf2(acc[am][an][0] + bsh[r],
                                                        acc[am][an][1] + bsh[r]);
                V[(size_t)(r + 8) * NU + np] = pack_bf2(acc[am][an][2] + bsh[r + 8],
                                                        acc[am][an][3] + bsh[r + 8]);
            }
    }
}

// ---------------- kernel 3: FUSED attention (energy+exp+PV+normalize) ----------------
// block: (n-tile 32) x (c-half 128) x batch = 256 blocks, 256 thr = 8 warps.
// loop over m in 64-chunks: phase A: E=exp(scale*q·k) -> smem P tile (bf16x2) + rsum regs;
// phase B: accO += V_chunk @ P^T. Epilogue normalizes by block-reduced rsum.
#define KLD 20     // KT/qT row stride (16 kpairs + 4 pad)
#define VLD 36     // V row stride (32 mpairs + 4 pad) - proven out_gemm pattern
#define PLD 36     // P tile row stride
#define FU_KT (64 * KLD)            // per stage
#define FU_V  (128 * VLD)           // per stage
#define OFF_V  (2 * FU_KT)
#define OFF_P  (OFF_V + 2 * FU_V)
#define OFF_Q  (OFF_P + 32 * PLD)
#define OFF_R  (OFF_Q + 32 * KLD)
#define FUSED_SMEM_BYTES ((OFF_R + 32 * 8 + 32) * 4)
__global__ __launch_bounds__(256) void fused_attn_kernel() {
    extern __shared__ __align__(16) uint sm[];
    uint*  KTs = sm;                 // [2][64*KLD]
    uint*  Vs  = sm + OFF_V;         // [2][128*VLD]
    uint*  Ps  = sm + OFF_P;         // [32*PLD]
    uint*  QTs = sm + OFF_Q;         // [32*KLD]
    float* red = (float*)(sm + OFF_R);   // [32][8]
    float* rsm = red + 32 * 8;           // [32] inverse row sums

    int b     = blockIdx.z;
    int chalf = blockIdx.y;
    int n0    = blockIdx.x * 32;
    int c0    = chalf * 128;

    int tid  = threadIdx.x;
    int lane = tid & 31, w = tid >> 5;
    int r4 = lane >> 2, q4 = lane & 3;
    int wc  = (w & 3) * 32;      // c offset within 128 (4 warps)
    int wn2 = (w >> 2) * 16;     // n offset within 32 (2 warps)

    const uint* QT = g_qT2 + (size_t)b * N * KU;
    const uint* KT = g_kT2 + (size_t)b * N * KU;
    const uint* V  = g_v   + (size_t)b * C * NU;

    int krow = tid >> 2, kseg = tid & 3;     // KT/qT staging: 64 rows x 4 segs
    int vrow = tid >> 3, vseg = (tid & 7) * 4;  // V staging: 128 rows x 8 segs, 4/thread

    // prologue: stage qT tile + chunk 0
    if (tid < 128)
        cp16((uint)__cvta_generic_to_shared(&QTs[krow * KLD + kseg * 4]),
             QT + (size_t)(n0 + krow) * KU + kseg * 4);
    cp16((uint)__cvta_generic_to_shared(&KTs[krow * KLD + kseg * 4]),
         KT + (size_t)krow * KU + kseg * 4);
#pragma unroll
    for (int i = 0; i < 4; i++) {
        int row = vrow + i * 32;
        cp16((uint)__cvta_generic_to_shared(&Vs[row * VLD + vseg]),
             V + (size_t)(c0 + row) * NU + vseg);
    }
    asm volatile("cp.async.commit_group;");

    float accO[2][2][4];
#pragma unroll
    for (int am = 0; am < 2; am++)
#pragma unroll
        for (int an = 0; an < 2; an++)
#pragma unroll
            for (int j = 0; j < 4; j++) accO[am][an][j] = 0.f;
    float rs[4] = {0.f, 0.f, 0.f, 0.f};
    uint a_all[2][2][4];   // [kstep][natom][frag]
    const float scale = 0.17677669529663687f;

    for (int ch = 0; ch < 16; ch++) {
        int s = ch & 1;
        asm volatile("cp.async.wait_group 0;");
        __syncthreads();

        // prefetch next chunk
        if (ch + 1 < 16) {
            int m0 = (ch + 1) * 64, mp = (ch + 1) * 32;
            uint* KTd = KTs + (s ^ 1) * FU_KT;
            uint* Vd  = Vs  + (s ^ 1) * FU_V;
            cp16((uint)__cvta_generic_to_shared(&KTd[krow * KLD + kseg * 4]),
                 KT + (size_t)(m0 + krow) * KU + kseg * 4);
#pragma unroll
            for (int i = 0; i < 4; i++) {
                int row = vrow + i * 32;
                cp16((uint)__cvta_generic_to_shared(&Vd[row * VLD + vseg]),
                     V + (size_t)(c0 + row) * NU + mp + vseg);
            }
            asm volatile("cp.async.commit_group;");
        }

        if (ch == 0) {
#pragma unroll
            for (int st = 0; st < 2; st++)
#pragma unroll
                for (int na = 0; na < 2; na++) {
                    int base = (na * 16 + r4) * KLD + st * 8 + q4;
                    a_all[st][na][0] = QTs[base];
                    a_all[st][na][1] = QTs[base + 8 * KLD];
                    a_all[st][na][2] = QTs[base + 4];
                    a_all[st][na][3] = QTs[base + 8 * KLD + 4];
                }
        }

        // ---- phase A: energies for this warp's 8 m-columns ----
        const uint* KTss = KTs + s * FU_KT;
        float e[2][4];
#pragma unroll
        for (int na = 0; na < 2; na++)
#pragma unroll
            for (int j = 0; j < 4; j++) e[na][j] = 0.f;
#pragma unroll
        for (int st = 0; st < 2; st++) {
            uint bb[2];
            int mb = (w * 8 + r4) * KLD + st * 8 + q4;
            bb[0] = KTss[mb];
            bb[1] = KTss[mb + 4];
#pragma unroll
            for (int na = 0; na < 2; na++)
                mma_bf16(e[na], a_all[st][na], bb);
        }
#pragma unroll
        for (int na = 0; na < 2; na++) {
            float e0 = fast_expf(e[na][0] * scale);
            float e1 = fast_expf(e[na][1] * scale);
            float e2 = fast_expf(e[na][2] * scale);
            float e3 = fast_expf(e[na][3] * scale);
            rs[na * 2 + 0] += e0 + e1;
            rs[na * 2 + 1] += e2 + e3;
            int pc = w * 4 + q4;
            Ps[(na * 16 + r4) * PLD + pc]     = pack_bf2(e0, e1);
            Ps[(na * 16 + r4 + 8) * PLD + pc] = pack_bf2(e2, e3);
        }
        __syncthreads();

        // ---- phase B: accO += V_chunk @ P^T ----
        const uint* Vss = Vs + s * FU_V;
#pragma unroll
        for (int k8 = 0; k8 < 32; k8 += 8) {
            uint a[2][4], bb2[2][2];
#pragma unroll
            for (int am = 0; am < 2; am++) {
                int base = (wc + am * 16 + r4) * VLD + k8 + q4;
                a[am][0] = Vss[base];
                a[am][1] = Vss[base + 8 * VLD];
                a[am][2] = Vss[base + 4];
                a[am][3] = Vss[base + 8 * VLD + 4];
            }
#pragma unroll
            for (int an = 0; an < 2; an++) {
                int base = (wn2 + an * 8 + r4) * PLD + k8 + q4;
                bb2[an][0] = Ps[base];
                bb2[an][1] = Ps[base + 4];
            }
#pragma unroll
            for (int am = 0; am < 2; am++)
#pragma unroll
                for (int an = 0; an < 2; an++)
                    mma_bf16(accO[am][an], a[am], bb2[an]);
        }
    }

    // ---- row-sum reduction ----
#pragma unroll
    for (int i = 0; i < 4; i++) {
        rs[i] += __shfl_xor_sync(0xFFFFFFFFu, rs[i], 1);
        rs[i] += __shfl_xor_sync(0xFFFFFFFFu, rs[i], 2);
    }
    __syncthreads();
    if (q4 == 0) {
        red[(r4)      * 8 + w] = rs[0];
        red[(r4 + 8)  * 8 + w] = rs[1];
        red[(r4 + 16) * 8 + w] = rs[2];
        red[(r4 + 24) * 8 + w] = rs[3];
    }
    __syncthreads();
    if (tid < 32) {
        float ssum = 0.f;
#pragma unroll
        for (int j = 0; j < 8; j++) ssum += red[tid * 8 + j];
        rsm[tid] = 1.0f / ssum;
    }
    __syncthreads();

    // ---- epilogue: normalize + store ----
    float* O = g_out + (size_t)b * C * N;
    int cc = q4 * 2;
#pragma unroll
    for (int am = 0; am < 2; am++)
#pragma unroll
        for (int an = 0; an < 2; an++) {
            int cr = c0 + wc + am * 16 + r4;
            int nl = wn2 + an * 8 + cc;
            float inv0 = rsm[nl], inv1 = rsm[nl + 1];
            int ncol = n0 + nl;
            float2 lo; lo.x = accO[am][an][0] * inv0; lo.y = accO[am][an][1] * inv1;
            float2 hi; hi.x = accO[am][an][2] * inv0; hi.y = accO[am][an][3] * inv1;
            *(float2*)(O + (size_t)cr * N + ncol)       = lo;
            *(float2*)(O + (size_t)(cr + 8) * N + ncol) = hi;
        }
}

// ---------------- kernel 4: nearest 8x upsample + residual ----------------
__global__ void upsample_add_kernel(const float* __restrict__ f, float* __restrict__ out) {
    size_t idx = (size_t)blockIdx.x * blockDim.x + threadIdx.x;
    int w4 = (int)(idx & 63);
    int h  = (int)((idx >> 6) & 255);
    size_t bc = idx >> 14;
    int hp = h >> 3;
    int wp = w4 >> 1;
    float s = g_out[bc * N + (size_t)hp * WP + wp];
    float4 a = ((const float4*)f)[idx];
    a.x += s; a.y += s; a.z += s; a.w += s;
    ((float4*)out)[idx] = a;
}

// ---------------- launch ----------------
extern "C" void kernel_launch(void* const* d_in, const int* in_sizes, int n_in,
                              void* d_out, int out_size) {
    const float* f  = (const float*)d_in[0];
    const float* qw = (const float*)d_in[1];
    const float* qb = (const float*)d_in[2];
    const float* kw = (const float*)d_in[3];
    const float* kb = (const float*)d_in[4];
    const float* vw = (const float*)d_in[5];
    const float* vb = (const float*)d_in[6];
    float* out = (float*)d_out;

    cudaFuncSetAttribute(fused_attn_kernel,
                         cudaFuncAttributeMaxDynamicSharedMemorySize, FUSED_SMEM_BYTES);

    prep_w_kernel<<<160, 256>>>(qw, kw, vw);
    avgpool_kernel<<<(BATCH * CP * N) / 256, 256>>>(f);
    qkv_mma_kernel<<<dim3(N / 64, 5, BATCH), 256>>>(qb, kb, vb);
    fused_attn_kernel<<<dim3(N / 32, 2, BATCH), 256, FUSED_SMEM_BYTES>>>();
    upsample_add_kernel<<<(BATCH * C * H * (W / 4)) / 256, 256>>>(f, out);
}